// round 4
// baseline (speedup 1.0000x reference)
#include <cuda_runtime.h>

#define TSTEPS 20
#define NROWS  32768
#define DEMB   64
#define DH     128
#define DOUT   5
#define GATES  512   // 4*DH
#define KTOT   192   // DEMB + DH
#define MTILE  32

// Persistent recurrent state (allowed scratch: __device__ globals)
__device__ float g_h[(size_t)NROWS * DH];
__device__ float g_c[(size_t)NROWS * DH];
__device__ int   g_mask_is_i32;   // 1 if mask stored as int32, 0 if 1-byte

// ---- packed f32x2 helpers (B300 FFMA2 fast path, PTX-only) ----
__device__ __forceinline__ unsigned long long pk2(float lo, float hi) {
    unsigned long long r;
    asm("mov.b64 %0, {%1, %2};" : "=l"(r) : "f"(lo), "f"(hi));
    return r;
}
__device__ __forceinline__ unsigned long long ffma2(unsigned long long a,
                                                    unsigned long long b,
                                                    unsigned long long c) {
    unsigned long long d;
    asm("fma.rn.f32x2 %0, %1, %2, %3;" : "=l"(d) : "l"(a), "l"(b), "l"(c));
    return d;
}
__device__ __forceinline__ float2 up2(unsigned long long v) {
    float lo, hi;
    asm("mov.b64 {%0, %1}, %2;" : "=f"(lo), "=f"(hi) : "l"(v));
    return make_float2(lo, hi);
}

__device__ __forceinline__ float sigf(float x) {
    return 1.0f / (1.0f + __expf(-x));
}
__device__ __forceinline__ float tanhf_fast(float x) {
    x = fminf(fmaxf(x, -30.0f), 30.0f);
    float e = __expf(-2.0f * x);
    return (1.0f - e) / (1.0f + e);
}

// Detect mask element width. Safe: reads first 4096 bytes, buffer is at least
// T*N = 655360 bytes in either interpretation. int32 masks (values 0/1, LE)
// have all bytes at idx%4!=0 equal to 0; a random uint8 0/1 mask has a one at
// a non-multiple-of-4 position with overwhelming probability.
__global__ void detect_mask_kernel(const unsigned char* __restrict__ m) {
    if (threadIdx.x == 0 && blockIdx.x == 0) {
        int is_i32 = 1;
        for (int i = 0; i < 4096; ++i) {
            if ((i & 3) != 0 && m[i] != 0) { is_i32 = 0; break; }
        }
        g_mask_is_i32 = is_i32;
    }
}

__global__ void init_state(const float* __restrict__ h0, const float* __restrict__ c0) {
    int i = blockIdx.x * blockDim.x + threadIdx.x;
    ((float4*)g_h)[i] = ((const float4*)h0)[i];
    ((float4*)g_c)[i] = ((const float4*)c0)[i];
}

__global__ __launch_bounds__(256, 2)
void lstm_step(const float* __restrict__ nodes_t,          // [N,2] slice for step t
               const unsigned char* __restrict__ mask_base,// full mask buffer
               int tstep,
               const float* __restrict__ W_embed, const float* __restrict__ b_embed,
               const float* __restrict__ W_ih,    const float* __restrict__ b_ih,
               const float* __restrict__ W_hh,    const float* __restrict__ b_hh,
               const float* __restrict__ W_out,   const float* __restrict__ b_out,
               float* __restrict__ out_t,                  // [N,5] slice for step t
               float* __restrict__ h_fin, float* __restrict__ c_fin,
               int is_last)
{
    __shared__ float As[KTOT][MTILE];          // A operand: emb (k<64) | h (k>=64), K-major
    __shared__ float outbuf[MTILE][DOUT];      // per-row output-projection reduction
    __shared__ unsigned char mask_s[MTILE];

    const int tid  = threadIdx.x;
    const int warp = tid >> 5;
    const int lane = tid & 31;
    const int row0 = blockIdx.x * MTILE;

    if (tid < MTILE) {
        const size_t ms = g_mask_is_i32 ? 4u : 1u;   // bytes per mask element
        mask_s[tid] = mask_base[((size_t)tstep * NROWS + row0 + tid) * ms];
    }
    if (tid < MTILE * DOUT) ((float*)outbuf)[tid] = 0.0f;

    // ---- stage embedding: warp w covers k in [8w, 8w+8), r = lane (conflict-free STS)
    {
        float2 x = *(const float2*)(nodes_t + (size_t)(row0 + lane) * 2);
        #pragma unroll
        for (int j = 0; j < 8; ++j) {
            int k = warp * 8 + j;
            float e = fmaf(x.x, W_embed[k], fmaf(x.y, W_embed[DEMB + k], b_embed[k]));
            As[k][lane] = fmaxf(e, 0.0f);
        }
    }
    // ---- stage h: warp w covers k in [16w, 16w+16), r = lane
    {
        const float* hrow = g_h + (size_t)(row0 + lane) * DH + warp * 16;
        #pragma unroll
        for (int jj = 0; jj < 4; ++jj) {
            float4 hv = *(const float4*)(hrow + jj * 4);
            int kb = DEMB + warp * 16 + jj * 4;
            As[kb + 0][lane] = hv.x;
            As[kb + 1][lane] = hv.y;
            As[kb + 2][lane] = hv.z;
            As[kb + 3][lane] = hv.w;
        }
    }
    __syncthreads();

    // ---- thread tile: 8 rows (rbase..rbase+7) x 8 cols = dims {d0,d0+1} x 4 gates
    const int cgid  = lane & 7;
    const int rbase = (lane >> 3) * 8;
    const int d0    = warp * 16 + cgid * 2;

    unsigned long long acc[8][4];
    #pragma unroll
    for (int g = 0; g < 4; ++g) {
        float2 bi = *(const float2*)(b_ih + d0 + 128 * g);
        float2 bh = *(const float2*)(b_hh + d0 + 128 * g);
        unsigned long long b2 = pk2(bi.x + bh.x, bi.y + bh.y);
        #pragma unroll
        for (int r = 0; r < 8; ++r) acc[r][g] = b2;
    }

    // ---- main K loop, segment 1: emb @ W_ih  (k = 0..63)
    {
        const float* wp = W_ih + d0;
        #pragma unroll 4
        for (int k = 0; k < DEMB; ++k) {
            unsigned long long w2[4];
            #pragma unroll
            for (int g = 0; g < 4; ++g)
                w2[g] = *(const unsigned long long*)(wp + (size_t)k * GATES + 128 * g);
            float4 a0 = *(const float4*)&As[k][rbase];
            float4 a1 = *(const float4*)&As[k][rbase + 4];
            float av[8] = {a0.x, a0.y, a0.z, a0.w, a1.x, a1.y, a1.z, a1.w};
            #pragma unroll
            for (int r = 0; r < 8; ++r) {
                unsigned long long a2 = pk2(av[r], av[r]);
                #pragma unroll
                for (int g = 0; g < 4; ++g) acc[r][g] = ffma2(a2, w2[g], acc[r][g]);
            }
        }
    }
    // ---- main K loop, segment 2: h @ W_hh  (k = 0..127)
    {
        const float* wp = W_hh + d0;
        #pragma unroll 4
        for (int k = 0; k < DH; ++k) {
            unsigned long long w2[4];
            #pragma unroll
            for (int g = 0; g < 4; ++g)
                w2[g] = *(const unsigned long long*)(wp + (size_t)k * GATES + 128 * g);
            float4 a0 = *(const float4*)&As[DEMB + k][rbase];
            float4 a1 = *(const float4*)&As[DEMB + k][rbase + 4];
            float av[8] = {a0.x, a0.y, a0.z, a0.w, a1.x, a1.y, a1.z, a1.w};
            #pragma unroll
            for (int r = 0; r < 8; ++r) {
                unsigned long long a2 = pk2(av[r], av[r]);
                #pragma unroll
                for (int g = 0; g < 4; ++g) acc[r][g] = ffma2(a2, w2[g], acc[r][g]);
            }
        }
    }

    // ---- LSTM epilogue: thread owns dims {d0,d0+1} with all four gates for its 8 rows
    const bool last = (is_last != 0);
    #pragma unroll
    for (int r = 0; r < 8; ++r) {
        const int srow = rbase + r;
        const int row  = row0 + srow;
        const bool m   = (mask_s[srow] != 0);

        float2 iv = up2(acc[r][0]);
        float2 fv = up2(acc[r][1]);
        float2 gv = up2(acc[r][2]);
        float2 ov = up2(acc[r][3]);
        float2 co = *(const float2*)(g_c + (size_t)row * DH + d0);

        float ivs[2] = {iv.x, iv.y}, fvs[2] = {fv.x, fv.y};
        float gvs[2] = {gv.x, gv.y}, ovs[2] = {ov.x, ov.y};
        float cold[2] = {co.x, co.y};
        float cn[2], hn[2];
        #pragma unroll
        for (int dd = 0; dd < 2; ++dd) {
            float i_ = sigf(ivs[dd]);
            float f_ = sigf(fvs[dd]);
            float o_ = sigf(ovs[dd]);
            float g_ = tanhf_fast(gvs[dd]);
            cn[dd] = f_ * cold[dd] + i_ * g_;
            hn[dd] = o_ * tanhf_fast(cn[dd]);
        }

        if (m) {
            #pragma unroll
            for (int q = 0; q < DOUT; ++q) {
                float p = fmaf(hn[0], W_out[(size_t)d0 * DOUT + q],
                               hn[1] * W_out[(size_t)(d0 + 1) * DOUT + q]);
                atomicAdd(&outbuf[srow][q], p);
            }
            if (!last) {
                *(float2*)(g_h + (size_t)row * DH + d0) = make_float2(hn[0], hn[1]);
                *(float2*)(g_c + (size_t)row * DH + d0) = make_float2(cn[0], cn[1]);
            }
        }
        if (last) {
            float h0o = As[DEMB + d0][srow];
            float h1o = As[DEMB + d0 + 1][srow];
            *(float2*)(h_fin + (size_t)row * DH + d0) =
                make_float2(m ? hn[0] : h0o, m ? hn[1] : h1o);
            *(float2*)(c_fin + (size_t)row * DH + d0) =
                make_float2(m ? cn[0] : cold[0], m ? cn[1] : cold[1]);
        }
    }

    __syncthreads();
    if (tid < MTILE * DOUT) {
        int r32 = tid / DOUT, q = tid % DOUT;
        float v = mask_s[r32] ? (outbuf[r32][q] + b_out[q]) : 0.0f;
        out_t[(size_t)(row0 + r32) * DOUT + q] = v;
    }
}

extern "C" void kernel_launch(void* const* d_in, const int* in_sizes, int n_in,
                              void* d_out, int out_size) {
    const float*         nodes   = (const float*)d_in[0];
    const unsigned char* mask    = (const unsigned char*)d_in[1];
    const float*         h0      = (const float*)d_in[2];
    const float*         c0      = (const float*)d_in[3];
    const float*         W_embed = (const float*)d_in[4];
    const float*         b_embed = (const float*)d_in[5];
    const float*         W_ih    = (const float*)d_in[6];
    const float*         b_ih    = (const float*)d_in[7];
    const float*         W_hh    = (const float*)d_in[8];
    const float*         b_hh    = (const float*)d_in[9];
    const float*         W_out   = (const float*)d_in[10];
    const float*         b_out   = (const float*)d_in[11];

    float* out   = (float*)d_out;
    float* h_fin = out + (size_t)TSTEPS * NROWS * DOUT;
    float* c_fin = h_fin + (size_t)NROWS * DH;

    detect_mask_kernel<<<1, 32>>>(mask);
    init_state<<<(NROWS * DH / 4) / 256, 256>>>(h0, c0);
    for (int t = 0; t < TSTEPS; ++t) {
        lstm_step<<<NROWS / MTILE, 256>>>(
            nodes + (size_t)t * NROWS * 2,
            mask, t,
            W_embed, b_embed, W_ih, b_ih, W_hh, b_hh, W_out, b_out,
            out + (size_t)t * NROWS * DOUT,
            h_fin, c_fin,
            (t == TSTEPS - 1) ? 1 : 0);
    }
}